// round 2
// baseline (speedup 1.0000x reference)
#include <cuda_runtime.h>
#include <mma.h>

using namespace nvcuda;

// Problem constants
#define Bv   2
#define Hv   16
#define Sv   2048
#define Dv   64

// Tiling
#define TQ   128      // query rows per CTA
#define TK   64       // key cols per k-tile
#define LD   68       // padded leading dim (64 + 4) -> 16B-aligned, bank-staggered
#define NTH  256      // 8 warps

// Shared memory layout (floats):
//   Qs  [TQ][LD]   = 8704
//   Ks  [TK][LD]   = 4352
//   Vs  [TK][LD]   = 4352
//   Ss  [TQ][LD]   = 8704   (S tile / P tile / final O staging)
//   rbuf[TQ]       = 128
#define SMEM_FLOATS (TQ*LD + TK*LD + TK*LD + TQ*LD + TQ)
#define SMEM_BYTES  (SMEM_FLOATS * 4)

__global__ __launch_bounds__(NTH)
void flashret_tf32_kernel(const float* __restrict__ q,
                          const float* __restrict__ k,
                          const float* __restrict__ v,
                          const float* __restrict__ mask,
                          float* __restrict__ out)
{
    extern __shared__ float sm[];
    float* Qs   = sm;
    float* Ks   = Qs + TQ * LD;
    float* Vs   = Ks + TK * LD;
    float* Ss   = Vs + TK * LD;
    float* rbuf = Ss + TQ * LD;

    const int bh   = blockIdx.y;     // 0..31  (b*H + h)
    const int qt   = blockIdx.x;     // 0..15  query tile
    const int tid  = threadIdx.x;
    const int warp = tid >> 5;       // 0..7 -> owns rows [16*warp, 16*warp+16)
    const int lane = tid & 31;

    const float* qp = q    + ((size_t)bh * Sv + (size_t)qt * TQ) * Dv;
    const float* kp = k    + (size_t)bh * Sv * Dv;
    const float* vp = v    + (size_t)bh * Sv * Dv;
    const float* mp = mask + ((size_t)bh * Sv + (size_t)qt * TQ) * (size_t)Sv;
    float*       op = out  + ((size_t)bh * Sv + (size_t)qt * TQ) * Dv;

    // ---- Load Q tile, convert to tf32 ----
    #pragma unroll
    for (int it = 0; it < (TQ * Dv / 4) / NTH; ++it) {
        int i   = tid + it * NTH;
        int row = i >> 4;
        int c   = (i & 15) << 2;
        float4 t = *(const float4*)(qp + (size_t)row * Dv + c);
        t.x = wmma::__float_to_tf32(t.x);
        t.y = wmma::__float_to_tf32(t.y);
        t.z = wmma::__float_to_tf32(t.z);
        t.w = wmma::__float_to_tf32(t.w);
        *(float4*)(Qs + row * LD + c) = t;
    }
    if (tid < TQ) rbuf[tid] = 0.0f;

    // O accumulators: each warp holds 16 rows x 64 cols = 4 frags of 16x16
    wmma::fragment<wmma::accumulator, 16, 16, 8, float> ofrag[4];
    #pragma unroll
    for (int n = 0; n < 4; ++n) wmma::fill_fragment(ofrag[n], 0.0f);

    __syncthreads();

    // ---- Main loop over key tiles ----
    for (int kt = 0; kt < Sv / TK; ++kt) {
        // Load K and V tiles (tf32-converted)
        const float* kpt = kp + (size_t)kt * TK * Dv;
        const float* vpt = vp + (size_t)kt * TK * Dv;
        #pragma unroll
        for (int it = 0; it < (TK * Dv / 4) / NTH; ++it) {
            int i   = tid + it * NTH;
            int row = i >> 4;
            int c   = (i & 15) << 2;
            float4 a = *(const float4*)(kpt + (size_t)row * Dv + c);
            a.x = wmma::__float_to_tf32(a.x);
            a.y = wmma::__float_to_tf32(a.y);
            a.z = wmma::__float_to_tf32(a.z);
            a.w = wmma::__float_to_tf32(a.w);
            *(float4*)(Ks + row * LD + c) = a;
            float4 b = *(const float4*)(vpt + (size_t)row * Dv + c);
            b.x = wmma::__float_to_tf32(b.x);
            b.y = wmma::__float_to_tf32(b.y);
            b.z = wmma::__float_to_tf32(b.z);
            b.w = wmma::__float_to_tf32(b.w);
            *(float4*)(Vs + row * LD + c) = b;
        }
        __syncthreads();

        // ---- GEMM1: S[16w:16w+16, 0:64] = Q_tile @ K_tileᵀ ----
        {
            wmma::fragment<wmma::matrix_a, 16, 16, 8, wmma::precision::tf32, wmma::row_major> af[8];
            #pragma unroll
            for (int kk = 0; kk < 8; ++kk)
                wmma::load_matrix_sync(af[kk], Qs + warp * 16 * LD + kk * 8, LD);

            #pragma unroll
            for (int n = 0; n < 4; ++n) {
                wmma::fragment<wmma::accumulator, 16, 16, 8, float> sf;
                wmma::fill_fragment(sf, 0.0f);
                #pragma unroll
                for (int kk = 0; kk < 8; ++kk) {
                    wmma::fragment<wmma::matrix_b, 16, 16, 8, wmma::precision::tf32, wmma::col_major> bf;
                    // B(k, n=j) = Ks[j*LD + k]  (col_major: k contiguous, col stride LD)
                    wmma::load_matrix_sync(bf, Ks + (n * 16) * LD + kk * 8, LD);
                    wmma::mma_sync(sf, af[kk], bf, sf);
                }
                wmma::store_matrix_sync(Ss + warp * 16 * LD + n * 16, sf, LD, wmma::mem_row_major);
            }
        }
        __syncthreads();

        // ---- Mask multiply (streamed from gmem) + |.| row reduction ----
        {
            const float* mpt = mp + (size_t)kt * TK;
            #pragma unroll
            for (int it = 0; it < (TQ * TK / 4) / NTH; ++it) {
                int i   = tid + it * NTH;
                int row = i >> 4;            // 16 float4 per row
                int c   = (i & 15) << 2;
                float4 m4 = *(const float4*)(mpt + (size_t)row * Sv + c);
                float4 s4 = *(float4*)(Ss + row * LD + c);
                float4 p;
                p.x = s4.x * m4.x;
                p.y = s4.y * m4.y;
                p.z = s4.z * m4.z;
                p.w = s4.w * m4.w;
                float asum = fabsf(p.x) + fabsf(p.y) + fabsf(p.z) + fabsf(p.w);
                // store tf32-rounded P for GEMM2 (r uses full fp32 products)
                p.x = wmma::__float_to_tf32(p.x);
                p.y = wmma::__float_to_tf32(p.y);
                p.z = wmma::__float_to_tf32(p.z);
                p.w = wmma::__float_to_tf32(p.w);
                *(float4*)(Ss + row * LD + c) = p;
                // reduce over the 16 lanes that share this row (xor of bits 0..3)
                #pragma unroll
                for (int o = 8; o >= 1; o >>= 1)
                    asum += __shfl_xor_sync(0xffffffffu, asum, o);
                if ((lane & 15) == 0) rbuf[row] += asum;   // single writer per row per tile
            }
        }
        __syncthreads();

        // ---- GEMM2: O[16w:16w+16, :] += P_tile @ V_tile ----
        {
            #pragma unroll
            for (int kk = 0; kk < 8; ++kk) {
                wmma::fragment<wmma::matrix_a, 16, 16, 8, wmma::precision::tf32, wmma::row_major> pa;
                wmma::load_matrix_sync(pa, Ss + warp * 16 * LD + kk * 8, LD);
                #pragma unroll
                for (int n = 0; n < 4; ++n) {
                    wmma::fragment<wmma::matrix_b, 16, 16, 8, wmma::precision::tf32, wmma::row_major> vb;
                    wmma::load_matrix_sync(vb, Vs + (kk * 8) * LD + n * 16, LD);
                    wmma::mma_sync(ofrag[n], pa, vb, ofrag[n]);
                }
            }
        }
        __syncthreads();   // protect Ks/Vs/Ss before next tile overwrites
    }

    // ---- Epilogue: stage O in smem, divide by max(r,1), write out ----
    #pragma unroll
    for (int n = 0; n < 4; ++n)
        wmma::store_matrix_sync(Ss + warp * 16 * LD + n * 16, ofrag[n], LD, wmma::mem_row_major);
    __syncthreads();

    #pragma unroll
    for (int it = 0; it < (TQ * Dv / 4) / NTH; ++it) {
        int i   = tid + it * NTH;
        int row = i >> 4;
        int c   = (i & 15) << 2;
        float rr  = rbuf[row];
        rr        = rr > 1.0f ? rr : 1.0f;
        float inv = 1.0f / rr;
        float4 t = *(float4*)(Ss + row * LD + c);
        t.x *= inv; t.y *= inv; t.z *= inv; t.w *= inv;
        *(float4*)(op + (size_t)row * Dv + c) = t;
    }
}

extern "C" void kernel_launch(void* const* d_in, const int* in_sizes, int n_in,
                              void* d_out, int out_size)
{
    const float* q    = (const float*)d_in[0];
    const float* k    = (const float*)d_in[1];
    const float* v    = (const float*)d_in[2];
    const float* mask = (const float*)d_in[3];
    float* out        = (float*)d_out;

    // >48KB dynamic smem requires opt-in (idempotent; capture-safe host call)
    cudaFuncSetAttribute(flashret_tf32_kernel,
                         cudaFuncAttributeMaxDynamicSharedMemorySize, SMEM_BYTES);

    dim3 grid(Sv / TQ, Bv * Hv);   // (16, 32) = 512 CTAs
    flashret_tf32_kernel<<<grid, NTH, SMEM_BYTES>>>(q, k, v, mask, out);
}

// round 5
// speedup vs baseline: 2.6041x; 2.6041x over previous
#include <cuda_runtime.h>
#include <cuda_fp16.h>
#include <cstdint>

// ---------------- problem constants ----------------
#define Bv   2
#define Hv   16
#define Sv   2048
#define Dv   64
#define TQ   128           // query rows per CTA (8 warps x 16 rows)
#define TK   64            // keys per tile
#define NT   (Sv / TK)     // 32 tiles
#define NTH  256

// ---------------- helpers ----------------
__device__ __forceinline__ uint32_t smem_u32(const void* p) {
    uint32_t a;
    asm("{ .reg .u64 t; cvta.to.shared.u64 t, %1; cvt.u32.u64 %0, t; }" : "=r"(a) : "l"(p));
    return a;
}
__device__ __forceinline__ uint32_t f2h2(float x, float y) {
    __half2 h = __floats2half2_rn(x, y);          // x -> lo half, y -> hi half
    return *reinterpret_cast<uint32_t*>(&h);
}
__device__ __forceinline__ void ldsm2(uint32_t& r0, uint32_t& r1, uint32_t a) {
    asm volatile("ldmatrix.sync.aligned.m8n8.x2.shared.b16 {%0,%1}, [%2];"
                 : "=r"(r0), "=r"(r1) : "r"(a));
}
__device__ __forceinline__ void ldsm2t(uint32_t& r0, uint32_t& r1, uint32_t a) {
    asm volatile("ldmatrix.sync.aligned.m8n8.x2.trans.shared.b16 {%0,%1}, [%2];"
                 : "=r"(r0), "=r"(r1) : "r"(a));
}
__device__ __forceinline__ void mma16816(float* c, const uint32_t* a, uint32_t b0, uint32_t b1) {
    asm volatile(
        "mma.sync.aligned.m16n8k16.row.col.f32.f16.f16.f32 "
        "{%0,%1,%2,%3}, {%4,%5,%6,%7}, {%8,%9}, {%0,%1,%2,%3};"
        : "+f"(c[0]), "+f"(c[1]), "+f"(c[2]), "+f"(c[3])
        : "r"(a[0]), "r"(a[1]), "r"(a[2]), "r"(a[3]), "r"(b0), "r"(b1));
}
// SW128 swizzle for a [64 rows][128B] fp16 tile: XOR 16B-chunk index by row%8
__device__ __forceinline__ uint32_t swz(int row, int cb) {
    return (uint32_t)(row * 128 + (cb ^ ((row & 7) << 4)));
}
__device__ __forceinline__ void sts16(uint32_t a, uint32_t x, uint32_t y, uint32_t z, uint32_t w) {
    asm volatile("st.shared.v4.b32 [%0], {%1,%2,%3,%4};"
                 :: "r"(a), "r"(x), "r"(y), "r"(z), "r"(w) : "memory");
}

// ---------------- kernel ----------------
__global__ __launch_bounds__(NTH, 2)
void flashret_fp16_kernel(const float* __restrict__ q,
                          const float* __restrict__ k,
                          const float* __restrict__ v,
                          const float* __restrict__ mask,
                          float* __restrict__ out)
{
    // K/V fp16 tiles, double buffered, SW128-swizzled: 4 x 8KB = 32KB
    __shared__ __align__(1024) uint8_t smem[32768];
    const uint32_t sb = smem_u32(smem);
    const uint32_t KB0 = sb, KB1 = sb + 8192, VB0 = sb + 16384, VB1 = sb + 24576;

    const int tid  = threadIdx.x;
    const int warp = tid >> 5;
    const int lane = tid & 31;
    const int tq   = lane >> 2;        // 0..7 (fragment row group)
    const int qd   = lane & 3;         // quad column
    const int R    = warp * 16;        // warp's q-row base within the CTA tile

    const int bh = blockIdx.y;         // 0..31
    const int qt = blockIdx.x;         // 0..15

    const size_t qrow = (size_t)bh * Sv + (size_t)qt * TQ + R + tq;
    const float* qlo = q + qrow * Dv;
    const float* qhi = qlo + 8 * Dv;
    const float* mlo = mask + qrow * (size_t)Sv;
    const float* mhi = mlo + (size_t)8 * Sv;
    float* olo = out + qrow * Dv;
    float* ohi = olo + 8 * Dv;
    const float* kg = k + (size_t)bh * Sv * Dv;
    const float* vg = v + (size_t)bh * Sv * Dv;

    // producer indices (each thread moves 2x 32B per tile per tensor)
    const int prow0 = tid >> 3,        pc0 = (tid & 7) * 8;
    const int prow1 = (256 + tid) >> 3, pc1 = pc0;     // idx+256 -> row+32
    const uint32_t so0 = swz(prow0, pc0 * 2);          // fp16 bytes = col*2
    const uint32_t so1 = swz(prow1 , pc1 * 2);

    // ---- Q A-fragments straight from gmem (fp16x2 packed) ----
    uint32_t qa[4][4];
    #pragma unroll
    for (int kb = 0; kb < 4; ++kb) {
        float2 a0 = *(const float2*)(qlo + kb * 16 + 2 * qd);
        float2 a1 = *(const float2*)(qhi + kb * 16 + 2 * qd);
        float2 a2 = *(const float2*)(qlo + kb * 16 + 8 + 2 * qd);
        float2 a3 = *(const float2*)(qhi + kb * 16 + 8 + 2 * qd);
        qa[kb][0] = f2h2(a0.x, a0.y);
        qa[kb][1] = f2h2(a1.x, a1.y);
        qa[kb][2] = f2h2(a2.x, a2.y);
        qa[kb][3] = f2h2(a3.x, a3.y);
    }

    // O accumulators (16x64 per warp) + row normalizers
    float o[8][4];
    #pragma unroll
    for (int j = 0; j < 8; ++j) { o[j][0] = o[j][1] = o[j][2] = o[j][3] = 0.0f; }
    float rlo = 0.0f, rhi = 0.0f;

    // ---- prologue: tile 0 into buffer 0 ----
    {
        float4 f0 = *(const float4*)(kg + prow0 * Dv + pc0);
        float4 f1 = *(const float4*)(kg + prow0 * Dv + pc0 + 4);
        float4 f2 = *(const float4*)(kg + prow1 * Dv + pc1);
        float4 f3 = *(const float4*)(kg + prow1 * Dv + pc1 + 4);
        float4 g0 = *(const float4*)(vg + prow0 * Dv + pc0);
        float4 g1 = *(const float4*)(vg + prow0 * Dv + pc0 + 4);
        float4 g2 = *(const float4*)(vg + prow1 * Dv + pc1);
        float4 g3 = *(const float4*)(vg + prow1 * Dv + pc1 + 4);
        sts16(KB0 + so0, f2h2(f0.x,f0.y), f2h2(f0.z,f0.w), f2h2(f1.x,f1.y), f2h2(f1.z,f1.w));
        sts16(KB0 + so1, f2h2(f2.x,f2.y), f2h2(f2.z,f2.w), f2h2(f3.x,f3.y), f2h2(f3.z,f3.w));
        sts16(VB0 + so0, f2h2(g0.x,g0.y), f2h2(g0.z,g0.w), f2h2(g1.x,g1.y), f2h2(g1.z,g1.w));
        sts16(VB0 + so1, f2h2(g2.x,g2.y), f2h2(g2.z,g2.w), f2h2(g3.x,g3.y), f2h2(g3.z,g3.w));
    }
    __syncthreads();

    // per-lane ldmatrix address components
    const int lrow8  = lane & 7;              // K ldsm row within 8-group
    const int lkhalf = ((lane >> 3) & 1) * 16; // K ldsm k-offset bytes
    const int lrow16 = lane & 15;             // V ldsm row within 16-group

    // ---- main loop over key tiles ----
    for (int kt = 0; kt < NT; ++kt) {
        const uint32_t KBc = (kt & 1) ? KB1 : KB0;
        const uint32_t VBc = (kt & 1) ? VB1 : VB0;
        const uint32_t KBn = (kt & 1) ? KB0 : KB1;
        const uint32_t VBn = (kt & 1) ? VB0 : VB1;
        const bool pf = (kt + 1) < NT;

        // prefetch next K tile (regs)
        float4 kf0, kf1, kf2, kf3;
        if (pf) {
            const float* kp = kg + (size_t)(kt + 1) * TK * Dv;
            kf0 = *(const float4*)(kp + prow0 * Dv + pc0);
            kf1 = *(const float4*)(kp + prow0 * Dv + pc0 + 4);
            kf2 = *(const float4*)(kp + prow1 * Dv + pc1);
            kf3 = *(const float4*)(kp + prow1 * Dv + pc1 + 4);
        }

        // ---- GEMM1: S(16x64) = Q @ K^T ----
        float c[8][4];
        #pragma unroll
        for (int j = 0; j < 8; ++j) { c[j][0] = c[j][1] = c[j][2] = c[j][3] = 0.0f; }
        #pragma unroll
        for (int j = 0; j < 8; ++j) {
            #pragma unroll
            for (int kb = 0; kb < 4; ++kb) {
                uint32_t b0, b1;
                ldsm2(b0, b1, KBc + swz(8 * j + lrow8, kb * 32 + lkhalf));
                mma16816(c[j], qa[kb], b0, b1);
            }
        }

        // store prefetched K into next buffer (LDG latency hidden by GEMM1)
        if (pf) {
            sts16(KBn + so0, f2h2(kf0.x,kf0.y), f2h2(kf0.z,kf0.w), f2h2(kf1.x,kf1.y), f2h2(kf1.z,kf1.w));
            sts16(KBn + so1, f2h2(kf2.x,kf2.y), f2h2(kf2.z,kf2.w), f2h2(kf3.x,kf3.y), f2h2(kf3.z,kf3.w));
        }

        // prefetch next V tile (regs)
        float4 vf0, vf1, vf2, vf3;
        if (pf) {
            const float* vp = vg + (size_t)(kt + 1) * TK * Dv;
            vf0 = *(const float4*)(vp + prow0 * Dv + pc0);
            vf1 = *(const float4*)(vp + prow0 * Dv + pc0 + 4);
            vf2 = *(const float4*)(vp + prow1 * Dv + pc1);
            vf3 = *(const float4*)(vp + prow1 * Dv + pc1 + 4);
        }

        // ---- mask multiply + |.| accumulation + pack to P A-frags ----
        uint32_t pa[4][4];
        const float* ml = mlo + (size_t)kt * TK;
        const float* mh = mhi + (size_t)kt * TK;
        #pragma unroll
        for (int j = 0; j < 8; ++j) {
            float2 am = *(const float2*)(ml + 8 * j + 2 * qd);
            float2 bm = *(const float2*)(mh + 8 * j + 2 * qd);
            float p0 = c[j][0] * am.x;
            float p1 = c[j][1] * am.y;
            float p2 = c[j][2] * bm.x;
            float p3 = c[j][3] * bm.y;
            rlo += fabsf(p0) + fabsf(p1);
            rhi += fabsf(p2) + fabsf(p3);
            const int kb = j >> 1, h = (j & 1) << 1;
            pa[kb][h]     = f2h2(p0, p1);   // rows lo, k-cols of this frag
            pa[kb][h + 1] = f2h2(p2, p3);   // rows hi
        }

        // ---- GEMM2: O(16x64) += P @ V ----
        #pragma unroll
        for (int j = 0; j < 8; ++j) {
            #pragma unroll
            for (int kb = 0; kb < 4; ++kb) {
                uint32_t b0, b1;
                ldsm2t(b0, b1, VBc + swz(kb * 16 + lrow16, j * 16));
                mma16816(o[j], pa[kb], b0, b1);
            }
        }

        // store prefetched V into next buffer (latency hidden by mask+GEMM2)
        if (pf) {
            sts16(VBn + so0, f2h2(vf0.x,vf0.y), f2h2(vf0.z,vf0.w), f2h2(vf1.x,vf1.y), f2h2(vf1.z,vf1.w));
            sts16(VBn + so1, f2h2(vf2.x,vf2.y), f2h2(vf2.z,vf2.w), f2h2(vf3.x,vf3.y), f2h2(vf3.z,vf3.w));
        }

        __syncthreads();   // one sync per tile: next buffers complete, current reads done
    }

    // ---- normalizer quad-reduction (cols live in the 4 quad lanes) ----
    rlo += __shfl_xor_sync(0xffffffffu, rlo, 1);
    rlo += __shfl_xor_sync(0xffffffffu, rlo, 2);
    rhi += __shfl_xor_sync(0xffffffffu, rhi, 1);
    rhi += __shfl_xor_sync(0xffffffffu, rhi, 2);
    const float il = 1.0f / fmaxf(rlo, 1.0f);
    const float ih = 1.0f / fmaxf(rhi, 1.0f);

    // ---- epilogue: scale + store ----
    #pragma unroll
    for (int j = 0; j < 8; ++j) {
        float2 lo2, hi2;
        lo2.x = o[j][0] * il;  lo2.y = o[j][1] * il;
        hi2.x = o[j][2] * ih;  hi2.y = o[j][3] * ih;
        *(float2*)(olo + 8 * j + 2 * qd) = lo2;
        *(float2*)(ohi + 8 * j + 2 * qd) = hi2;
    }
}

extern "C" void kernel_launch(void* const* d_in, const int* in_sizes, int n_in,
                              void* d_out, int out_size)
{
    const float* q    = (const float*)d_in[0];
    const float* k    = (const float*)d_in[1];
    const float* v    = (const float*)d_in[2];
    const float* mask = (const float*)d_in[3];
    float* out        = (float*)d_out;

    dim3 grid(Sv / TQ, Bv * Hv);   // (16, 32) = 512 CTAs
    flashret_fp16_kernel<<<grid, NTH>>>(q, k, v, mask, out);
}